// round 2
// baseline (speedup 1.0000x reference)
#include <cuda_runtime.h>
#include <cstdint>

// GeneralAttention: B=2,H=16,S=2048,D=64 fp32, mask [B,1,S,S] int32 (0 -> fill -32768)
// Flash-attention, fp32 via packed fma.rn.f32x2 (2x FFMA throughput on sm_103a).

#define Bc 2
#define Hc 16
#define Sc 2048
#define Dc 64
#define BR 128
#define BKT 128
#define NT 256

// smem layout (floats):
//   Qs  [64][128]           @ 0        (8192)   Q transposed, d-major
//   Ks2 [128][132]          @ 8192     (16896)  K duplicated pairs (k,k) along d  -- aliased by Ps after QK
//   Vs2 [128][128]          @ 25088    (16384)  V duplicated pairs (v,v) along d
#define QS_OFF   0
#define KS_OFF   8192
#define PS_OFF   8192          /* Ps aliases Ks2, stride 132 */
#define VS_OFF   25088
#define SMEM_FLOATS (8192 + 16896 + 16384)
#define SMEM_BYTES (SMEM_FLOATS * 4)

#define LOG2E 1.4426950408889634f

using u64 = unsigned long long;

__device__ __forceinline__ u64 ffma2(u64 a, u64 b, u64 c) {
    u64 d;
    asm("fma.rn.f32x2 %0, %1, %2, %3;" : "=l"(d) : "l"(a), "l"(b), "l"(c));
    return d;
}
__device__ __forceinline__ u64 fmul2(u64 a, u64 b) {
    u64 d;
    asm("mul.rn.f32x2 %0, %1, %2;" : "=l"(d) : "l"(a), "l"(b));
    return d;
}
__device__ __forceinline__ u64 pk2(float lo, float hi) {
    u64 r;
    asm("mov.b64 %0, {%1, %2};" : "=l"(r) : "f"(lo), "f"(hi));
    return r;
}
__device__ __forceinline__ void unpk(u64 v, float& lo, float& hi) {
    asm("mov.b64 {%0, %1}, %2;" : "=f"(lo), "=f"(hi) : "l"(v));
}
__device__ __forceinline__ float ex2(float x) {
    float r;
    asm("ex2.approx.ftz.f32 %0, %1;" : "=f"(r) : "f"(x));
    return r;
}

__global__ void __launch_bounds__(NT, 1)
attn_kernel(const float* __restrict__ Q, const float* __restrict__ K,
            const float* __restrict__ V, const int* __restrict__ Mask,
            float* __restrict__ Out)
{
    extern __shared__ float sm[];
    float* Qs  = sm + QS_OFF;   // [64][128]
    float* Ks2 = sm + KS_OFF;   // [128][132]
    float* Ps  = sm + PS_OFF;   // [128][132] (alias of Ks2)
    float* Vs2 = sm + VS_OFF;   // [128][128]

    const int tid = threadIdx.x;
    const int tx = tid & 15;        // 0..15
    const int ty = tid >> 4;        // 0..15
    const int ty8 = ty * 8;
    const int qt = blockIdx.x;      // q tile
    const int bh = blockIdx.y;      // b*H + h
    const int b  = bh >> 4;         // H = 16
    const int q0 = qt * BR;

    const float* Qg = Q + ((size_t)bh * Sc + q0) * Dc;
    const float* Kg = K + (size_t)bh * Sc * Dc;
    const float* Vg = V + (size_t)bh * Sc * Dc;
    const int*   Mg = Mask + (size_t)b * Sc * Sc + (size_t)q0 * Sc;
    float*       Og = Out + ((size_t)bh * Sc + q0) * Dc;

    // ---- load Q tile transposed: Qs[d][r] (one-time) ----
    #pragma unroll
    for (int it = 0; it < 8; ++it) {
        int i  = tid + NT * it;        // float4 index over [128][16]
        int r  = i >> 4;
        int d4 = i & 15;
        float4 v = ((const float4*)Qg)[i];
        Qs[(d4 * 4 + 0) * 128 + r] = v.x;
        Qs[(d4 * 4 + 1) * 128 + r] = v.y;
        Qs[(d4 * 4 + 2) * 128 + r] = v.z;
        Qs[(d4 * 4 + 3) * 128 + r] = v.w;
    }

    float m_i[8], l_i[8];
    #pragma unroll
    for (int i = 0; i < 8; ++i) { m_i[i] = -1e30f; l_i[i] = 0.0f; }

    u64 O2[4][4];   // row-pairs (2p,2p+1) x cols (4*tx + c)
    #pragma unroll
    for (int p = 0; p < 4; ++p)
        #pragma unroll
        for (int c = 0; c < 4; ++c) O2[p][c] = 0ull;

    for (int kt = 0; kt < Sc / BKT; ++kt) {
        __syncthreads();   // previous PV reads of Ps/Vs2 done

        // ---- load K,V tiles with value duplication ----
        const float4* Kt = (const float4*)(Kg + (size_t)kt * BKT * Dc);
        const float4* Vt = (const float4*)(Vg + (size_t)kt * BKT * Dc);
        #pragma unroll
        for (int it = 0; it < 8; ++it) {
            int i  = tid + NT * it;
            int rr = i >> 4;
            int d4 = i & 15;
            float4 kv = Kt[i];
            float2* kd = (float2*)&Ks2[rr * 132 + d4 * 8];
            kd[0] = make_float2(kv.x, kv.x);
            kd[1] = make_float2(kv.y, kv.y);
            kd[2] = make_float2(kv.z, kv.z);
            kd[3] = make_float2(kv.w, kv.w);
            float4 vv = Vt[i];
            float2* vd = (float2*)&Vs2[rr * 128 + d4 * 8];
            vd[0] = make_float2(vv.x, vv.x);
            vd[1] = make_float2(vv.y, vv.y);
            vd[2] = make_float2(vv.z, vv.z);
            vd[3] = make_float2(vv.w, vv.w);
        }
        __syncthreads();

        // ---- S = Q K^T  (rows ty8..ty8+7, cols tx+16j) ----
        u64 acc2[4][8];
        #pragma unroll
        for (int p = 0; p < 4; ++p)
            #pragma unroll
            for (int j = 0; j < 8; ++j) acc2[p][j] = 0ull;

        #pragma unroll 2
        for (int d2 = 0; d2 < 32; ++d2) {
            const float* qp = &Qs[(2 * d2) * 128 + ty8];
            ulonglong2 qa0 = *(const ulonglong2*)(qp);
            ulonglong2 qb0 = *(const ulonglong2*)(qp + 4);
            ulonglong2 qa1 = *(const ulonglong2*)(qp + 128);
            ulonglong2 qb1 = *(const ulonglong2*)(qp + 132);
            #pragma unroll
            for (int j = 0; j < 8; ++j) {
                ulonglong2 kv = *(const ulonglong2*)&Ks2[(tx + 16 * j) * 132 + 4 * d2];
                acc2[0][j] = ffma2(qa0.x, kv.x, acc2[0][j]);
                acc2[1][j] = ffma2(qa0.y, kv.x, acc2[1][j]);
                acc2[2][j] = ffma2(qb0.x, kv.x, acc2[2][j]);
                acc2[3][j] = ffma2(qb0.y, kv.x, acc2[3][j]);
                acc2[0][j] = ffma2(qa1.x, kv.y, acc2[0][j]);
                acc2[1][j] = ffma2(qa1.y, kv.y, acc2[1][j]);
                acc2[2][j] = ffma2(qb1.x, kv.y, acc2[2][j]);
                acc2[3][j] = ffma2(qb1.y, kv.y, acc2[3][j]);
            }
        }

        // ---- unpack scores ----
        float sv[8][8];
        #pragma unroll
        for (int p = 0; p < 4; ++p)
            #pragma unroll
            for (int j = 0; j < 8; ++j)
                unpk(acc2[p][j], sv[2 * p][j], sv[2 * p + 1][j]);

        // ---- mask + online softmax ----
        float alpha_r[8];
        #pragma unroll
        for (int i = 0; i < 8; ++i) {
            const int* mrow = Mg + (size_t)(ty8 + i) * Sc + kt * BKT + tx;
            int mk[8];
            #pragma unroll
            for (int j = 0; j < 8; ++j) mk[j] = mrow[16 * j];

            float mx = -1e30f;
            #pragma unroll
            for (int j = 0; j < 8; ++j) {
                float s = (mk[j] == 0) ? -32768.0f : sv[i][j] * 0.125f;
                sv[i][j] = s;
                mx = fmaxf(mx, s);
            }
            mx = fmaxf(mx, __shfl_xor_sync(0xffffffffu, mx, 1));
            mx = fmaxf(mx, __shfl_xor_sync(0xffffffffu, mx, 2));
            mx = fmaxf(mx, __shfl_xor_sync(0xffffffffu, mx, 4));
            mx = fmaxf(mx, __shfl_xor_sync(0xffffffffu, mx, 8));

            float mnew = fmaxf(m_i[i], mx);
            alpha_r[i] = ex2((m_i[i] - mnew) * LOG2E);
            m_i[i] = mnew;

            float rs = 0.0f;
            #pragma unroll
            for (int j = 0; j < 8; ++j) {
                float p = ex2((sv[i][j] - mnew) * LOG2E);
                sv[i][j] = p;
                rs += p;
            }
            rs += __shfl_xor_sync(0xffffffffu, rs, 1);
            rs += __shfl_xor_sync(0xffffffffu, rs, 2);
            rs += __shfl_xor_sync(0xffffffffu, rs, 4);
            rs += __shfl_xor_sync(0xffffffffu, rs, 8);
            l_i[i] = l_i[i] * alpha_r[i] + rs;
        }

        // ---- rescale O ----
        #pragma unroll
        for (int p = 0; p < 4; ++p) {
            u64 a2 = pk2(alpha_r[2 * p], alpha_r[2 * p + 1]);
            #pragma unroll
            for (int c = 0; c < 4; ++c) O2[p][c] = fmul2(O2[p][c], a2);
        }

        __syncthreads();   // all QK reads of Ks2 done before overwriting with Ps

        // ---- store P transposed: Ps[k][r] ----
        #pragma unroll
        for (int j = 0; j < 8; ++j) {
            float* pdst = &Ps[(tx + 16 * j) * 132 + ty8];
            #pragma unroll
            for (int i = 0; i < 8; ++i) pdst[i] = sv[i][j];
        }
        __syncthreads();

        // ---- O += P @ V ----
        #pragma unroll 4
        for (int k = 0; k < BKT; ++k) {
            const float* pp = &Ps[k * 132 + ty8];
            ulonglong2 pa = *(const ulonglong2*)(pp);
            ulonglong2 pb = *(const ulonglong2*)(pp + 4);
            const float* vp = &Vs2[k * 128 + tx * 8];
            ulonglong2 va = *(const ulonglong2*)(vp);
            ulonglong2 vb = *(const ulonglong2*)(vp + 4);
            O2[0][0] = ffma2(pa.x, va.x, O2[0][0]);
            O2[0][1] = ffma2(pa.x, va.y, O2[0][1]);
            O2[0][2] = ffma2(pa.x, vb.x, O2[0][2]);
            O2[0][3] = ffma2(pa.x, vb.y, O2[0][3]);
            O2[1][0] = ffma2(pa.y, va.x, O2[1][0]);
            O2[1][1] = ffma2(pa.y, va.y, O2[1][1]);
            O2[1][2] = ffma2(pa.y, vb.x, O2[1][2]);
            O2[1][3] = ffma2(pa.y, vb.y, O2[1][3]);
            O2[2][0] = ffma2(pb.x, va.x, O2[2][0]);
            O2[2][1] = ffma2(pb.x, va.y, O2[2][1]);
            O2[2][2] = ffma2(pb.x, vb.x, O2[2][2]);
            O2[2][3] = ffma2(pb.x, vb.y, O2[2][3]);
            O2[3][0] = ffma2(pb.y, va.x, O2[3][0]);
            O2[3][1] = ffma2(pb.y, va.y, O2[3][1]);
            O2[3][2] = ffma2(pb.y, vb.x, O2[3][2]);
            O2[3][3] = ffma2(pb.y, vb.y, O2[3][3]);
        }
    }

    // ---- epilogue: normalize + write ----
    float invl[8];
    #pragma unroll
    for (int i = 0; i < 8; ++i) invl[i] = 1.0f / l_i[i];

    #pragma unroll
    for (int p = 0; p < 4; ++p) {
        float lo0, hi0, lo1, hi1, lo2, hi2, lo3, hi3;
        unpk(O2[p][0], lo0, hi0);
        unpk(O2[p][1], lo1, hi1);
        unpk(O2[p][2], lo2, hi2);
        unpk(O2[p][3], lo3, hi3);
        int r0 = ty8 + 2 * p;
        float4 o_lo = make_float4(lo0 * invl[2 * p], lo1 * invl[2 * p],
                                  lo2 * invl[2 * p], lo3 * invl[2 * p]);
        float4 o_hi = make_float4(hi0 * invl[2 * p + 1], hi1 * invl[2 * p + 1],
                                  hi2 * invl[2 * p + 1], hi3 * invl[2 * p + 1]);
        ((float4*)(Og + (size_t)r0 * Dc))[tx] = o_lo;
        ((float4*)(Og + (size_t)(r0 + 1) * Dc))[tx] = o_hi;
    }
}

extern "C" void kernel_launch(void* const* d_in, const int* in_sizes, int n_in,
                              void* d_out, int out_size)
{
    const float* Q    = (const float*)d_in[0];
    const float* K    = (const float*)d_in[1];
    const float* V    = (const float*)d_in[2];
    const int*   mask = (const int*)d_in[3];
    float* out = (float*)d_out;

    cudaFuncSetAttribute(attn_kernel, cudaFuncAttributeMaxDynamicSharedMemorySize, SMEM_BYTES);
    dim3 grid(Sc / BR, Bc * Hc);
    attn_kernel<<<grid, NT, SMEM_BYTES>>>(Q, K, V, mask, out);
}